// round 1
// baseline (speedup 1.0000x reference)
#include <cuda_runtime.h>
#include <math.h>

#define NB 4
#define NW 2048
#define DM 1024
#define NH 16
#define DK 64
#define MT (NB*NW)          // 8192 total rows
#define MWPR (NW/32)        // 64 packed mask words per row
#define FROW 68             // padded smem row (floats), 68*4B = 16B-aligned stride

// ---- device scratch (static: no allocations allowed) ----
__device__ float g_q[NB*NH*NW*DK];      // 33.5 MB, [b][h][t][d]
__device__ float g_k[NB*NH*NW*DK];
__device__ float g_v[NB*NH*NW*DK];
__device__ float g_attn[NB*NW*DM];      // [b][t][h*64+d]
__device__ unsigned g_mb[NB*NW*MWPR];   // packed mask bits, 2 MB

// ============================================================
// Kernel 1: pack int32 mask -> 1 bit. One warp produces one word.
// ============================================================
__global__ void __launch_bounds__(256) pack_mask_kernel(const int* __restrict__ mask) {
    int gt = blockIdx.x * 256 + threadIdx.x;   // grid sized exactly: no bounds check
    int word = gt >> 5;
    int lane = gt & 31;
    int v = mask[word * 32 + lane];
    unsigned b = __ballot_sync(0xffffffffu, v != 0);
    if (lane == 0) g_mb[word] = b;
}

// ============================================================
// Shared GEMM tile body: C[64x64] = X[64xK] * W[64xK]^T (both K-contiguous)
// 256 threads, 4x4 micro-tile per thread, BK=16.
// ============================================================
__device__ __forceinline__ void gemm_tile(const float* __restrict__ X,
                                          const float* __restrict__ W,
                                          int m0, int n0, float acc[4][4],
                                          float (*As)[FROW], float (*Bs)[FROW]) {
    int tid = threadIdx.x;
    int lm = tid >> 2, kq = tid & 3;     // loader mapping: one float4 per thread per tile
    int ty = tid >> 4, tx = tid & 15;    // compute mapping
    for (int k0 = 0; k0 < DM; k0 += 16) {
        float4 av = *(const float4*)&X[(m0 + lm) * DM + k0 + kq * 4];
        float4 bv = *(const float4*)&W[(n0 + lm) * DM + k0 + kq * 4];
        As[kq*4+0][lm] = av.x; As[kq*4+1][lm] = av.y;
        As[kq*4+2][lm] = av.z; As[kq*4+3][lm] = av.w;
        Bs[kq*4+0][lm] = bv.x; Bs[kq*4+1][lm] = bv.y;
        Bs[kq*4+2][lm] = bv.z; Bs[kq*4+3][lm] = bv.w;
        __syncthreads();
        #pragma unroll
        for (int kk = 0; kk < 16; kk++) {
            float4 a4 = *(const float4*)&As[kk][ty * 4];
            float4 b4 = *(const float4*)&Bs[kk][tx * 4];
            float a[4] = {a4.x, a4.y, a4.z, a4.w};
            float b[4] = {b4.x, b4.y, b4.z, b4.w};
            #pragma unroll
            for (int i = 0; i < 4; i++)
                #pragma unroll
                for (int j = 0; j < 4; j++)
                    acc[i][j] += a[i] * b[j];
        }
        __syncthreads();
    }
}

// ============================================================
// Kernel 2: fused Q/K/V projections (grid.z selects which), output head-major
// ============================================================
__global__ void __launch_bounds__(256) proj_gemm_kernel(
    const float* __restrict__ Qi, const float* __restrict__ Ki, const float* __restrict__ Vi,
    const float* __restrict__ Wq, const float* __restrict__ Wk, const float* __restrict__ Wv)
{
    __shared__ float As[16][FROW], Bs[16][FROW];
    int which = blockIdx.z;
    const float* X = (which == 0) ? Qi : (which == 1) ? Ki : Vi;
    const float* W = (which == 0) ? Wq : (which == 1) ? Wk : Wv;
    float* dst     = (which == 0) ? g_q : (which == 1) ? g_k : g_v;
    int m0 = blockIdx.y * 64, n0 = blockIdx.x * 64;
    float acc[4][4] = {};
    gemm_tile(X, W, m0, n0, acc, As, Bs);
    int tid = threadIdx.x, ty = tid >> 4, tx = tid & 15;
    int h = n0 >> 6;   // BN==64 => whole n-tile is exactly one head
    #pragma unroll
    for (int i = 0; i < 4; i++) {
        int m = m0 + ty * 4 + i;
        int b = m >> 11, t = m & (NW - 1);
        float4 o = make_float4(acc[i][0], acc[i][1], acc[i][2], acc[i][3]);
        *(float4*)&dst[((b * NH + h) * NW + t) * DK + tx * 4] = o;
    }
}

// ============================================================
// Kernel 3: flash attention, one CTA = (b, h, 64 q-rows). fp32.
// smem: Qs[d][m], KPs (K tile [d][n], reused as P [n][m]), Vs[n][d], mask words
// ============================================================
__global__ void __launch_bounds__(256) flash_kernel() {
    extern __shared__ float sm[];
    float* Qs  = sm;                    // [64][FROW]  layout [d][m]
    float* KPs = sm + 64 * FROW;        // [64][FROW]  K as [d][n], then P as [n][m]
    float* Vs  = sm + 2 * 64 * FROW;    // [64][FROW]  [n][d]
    unsigned* mw = (unsigned*)(sm + 3 * 64 * FROW);  // [64][2]

    int b = blockIdx.z, h = blockIdx.y, q0 = blockIdx.x * 64;
    int tid = threadIdx.x;
    int ty = tid >> 4, tx = tid & 15;

    const float* qp = g_q + ((b * NH + h) * NW + q0) * DK;
    const float* kb = g_k + (b * NH + h) * NW * DK;
    const float* vb = g_v + (b * NH + h) * NW * DK;

    // Load Q tile transposed [d][m], pre-scaled by 1/sqrt(DK)=0.125
    #pragma unroll
    for (int it = 0; it < 4; it++) {
        int idx = tid + it * 256;
        int m = idx >> 4, dq = idx & 15;
        float4 v = *(const float4*)&qp[m * DK + dq * 4];
        Qs[(dq*4+0)*FROW + m] = v.x * 0.125f;
        Qs[(dq*4+1)*FROW + m] = v.y * 0.125f;
        Qs[(dq*4+2)*FROW + m] = v.z * 0.125f;
        Qs[(dq*4+3)*FROW + m] = v.w * 0.125f;
    }

    float om[4], ol[4], acc[4][4];
    #pragma unroll
    for (int i = 0; i < 4; i++) {
        om[i] = -INFINITY; ol[i] = 0.f;
        #pragma unroll
        for (int j = 0; j < 4; j++) acc[i][j] = 0.f;
    }

    for (int kt = 0; kt < NW / 64; kt++) {
        __syncthreads();   // previous PV reads of KPs/Vs done (also covers Qs on kt=0)
        const float* kp = kb + kt * 64 * DK;
        const float* vp = vb + kt * 64 * DK;
        #pragma unroll
        for (int it = 0; it < 4; it++) {
            int idx = tid + it * 256;
            int n = idx >> 4, dq = idx & 15;
            float4 kv = *(const float4*)&kp[n * DK + dq * 4];
            KPs[(dq*4+0)*FROW + n] = kv.x;
            KPs[(dq*4+1)*FROW + n] = kv.y;
            KPs[(dq*4+2)*FROW + n] = kv.z;
            KPs[(dq*4+3)*FROW + n] = kv.w;
            float4 vv = *(const float4*)&vp[n * DK + dq * 4];
            *(float4*)&Vs[n * FROW + dq * 4] = vv;
        }
        if (tid < 128) {
            int r = tid >> 1, w = tid & 1;
            mw[r * 2 + w] = g_mb[(b * NW + q0 + r) * MWPR + kt * 2 + w];
        }
        __syncthreads();

        // S = Qs^T * Ks  (4x4 per thread)
        float s[4][4] = {};
        #pragma unroll 16
        for (int d = 0; d < DK; d++) {
            float4 a4 = *(const float4*)&Qs[d * FROW + ty * 4];
            float4 b4 = *(const float4*)&KPs[d * FROW + tx * 4];
            float a[4] = {a4.x, a4.y, a4.z, a4.w};
            float bb[4] = {b4.x, b4.y, b4.z, b4.w};
            #pragma unroll
            for (int i = 0; i < 4; i++)
                #pragma unroll
                for (int j = 0; j < 4; j++)
                    s[i][j] += a[i] * bb[j];
        }

        // mask + per-thread row max
        float tm[4], rs[4];
        #pragma unroll
        for (int i = 0; i < 4; i++) {
            unsigned w0 = mw[(ty*4+i)*2 + 0];
            unsigned w1 = mw[(ty*4+i)*2 + 1];
            tm[i] = -INFINITY;
            #pragma unroll
            for (int j = 0; j < 4; j++) {
                int n = tx * 4 + j;
                unsigned bits = (n < 32) ? w0 : w1;
                if (!((bits >> (n & 31)) & 1u)) s[i][j] = -1e9f;
                tm[i] = fmaxf(tm[i], s[i][j]);
            }
        }
        // reduce max across the 16-lane tx group (stays within half-warp)
        #pragma unroll
        for (int i = 0; i < 4; i++) {
            tm[i] = fmaxf(tm[i], __shfl_xor_sync(0xffffffffu, tm[i], 8));
            tm[i] = fmaxf(tm[i], __shfl_xor_sync(0xffffffffu, tm[i], 4));
            tm[i] = fmaxf(tm[i], __shfl_xor_sync(0xffffffffu, tm[i], 2));
            tm[i] = fmaxf(tm[i], __shfl_xor_sync(0xffffffffu, tm[i], 1));
        }
        // online softmax update
        #pragma unroll
        for (int i = 0; i < 4; i++) {
            float nm = fmaxf(om[i], tm[i]);
            float sc = __expf(om[i] - nm);   // exp(-inf)=0 on first tile
            rs[i] = 0.f;
            #pragma unroll
            for (int j = 0; j < 4; j++) {
                s[i][j] = __expf(s[i][j] - nm);
                rs[i] += s[i][j];
            }
            om[i] = nm;
            ol[i] *= sc;
            #pragma unroll
            for (int j = 0; j < 4; j++) acc[i][j] *= sc;
        }
        #pragma unroll
        for (int i = 0; i < 4; i++) {
            rs[i] += __shfl_xor_sync(0xffffffffu, rs[i], 8);
            rs[i] += __shfl_xor_sync(0xffffffffu, rs[i], 4);
            rs[i] += __shfl_xor_sync(0xffffffffu, rs[i], 2);
            rs[i] += __shfl_xor_sync(0xffffffffu, rs[i], 1);
            ol[i] += rs[i];
        }

        __syncthreads();   // everyone done reading K tile before P overwrites it
        #pragma unroll
        for (int i = 0; i < 4; i++)
            #pragma unroll
            for (int j = 0; j < 4; j++)
                KPs[(tx*4+j)*FROW + ty*4+i] = s[i][j];   // P stored [n][m]
        __syncthreads();

        // O += P * V
        #pragma unroll 16
        for (int n = 0; n < 64; n++) {
            float4 a4 = *(const float4*)&KPs[n * FROW + ty * 4];
            float4 v4 = *(const float4*)&Vs[n * FROW + tx * 4];
            float a[4] = {a4.x, a4.y, a4.z, a4.w};
            float vv[4] = {v4.x, v4.y, v4.z, v4.w};
            #pragma unroll
            for (int i = 0; i < 4; i++)
                #pragma unroll
                for (int j = 0; j < 4; j++)
                    acc[i][j] += a[i] * vv[j];
        }
    }

    // epilogue: normalize and write [b][t][h*64+d]
    #pragma unroll
    for (int i = 0; i < 4; i++) {
        float inv = 1.f / ol[i];
        int t = q0 + ty * 4 + i;
        float4 o = make_float4(acc[i][0]*inv, acc[i][1]*inv, acc[i][2]*inv, acc[i][3]*inv);
        *(float4*)&g_attn[(b * NW + t) * DM + h * DK + tx * 4] = o;
    }
}

// ============================================================
// Kernel 4: output projection: out = attn @ Wo^T (plain row-major out)
// ============================================================
__global__ void __launch_bounds__(256) out_gemm_kernel(const float* __restrict__ Wo,
                                                       float* __restrict__ out)
{
    __shared__ float As[16][FROW], Bs[16][FROW];
    int m0 = blockIdx.y * 64, n0 = blockIdx.x * 64;
    float acc[4][4] = {};
    gemm_tile(g_attn, Wo, m0, n0, acc, As, Bs);
    int tid = threadIdx.x, ty = tid >> 4, tx = tid & 15;
    #pragma unroll
    for (int i = 0; i < 4; i++) {
        float4 o = make_float4(acc[i][0], acc[i][1], acc[i][2], acc[i][3]);
        *(float4*)&out[(m0 + ty * 4 + i) * DM + n0 + tx * 4] = o;
    }
}

// ============================================================
extern "C" void kernel_launch(void* const* d_in, const int* in_sizes, int n_in,
                              void* d_out, int out_size) {
    const float* Q  = (const float*)d_in[0];
    const float* K  = (const float*)d_in[1];
    const float* V  = (const float*)d_in[2];
    const int* mask = (const int*)d_in[3];
    const float* Wq = (const float*)d_in[4];
    const float* Wk = (const float*)d_in[5];
    const float* Wv = (const float*)d_in[6];
    const float* Wo = (const float*)d_in[7];
    float* out = (float*)d_out;

    size_t smem = (size_t)(3 * 64 * FROW + 128) * sizeof(float);   // 52,736 B
    cudaFuncSetAttribute(flash_kernel, cudaFuncAttributeMaxDynamicSharedMemorySize, (int)smem);

    pack_mask_kernel<<<(NB * NW * NW) / 256, 256>>>(mask);
    proj_gemm_kernel<<<dim3(DM / 64, MT / 64, 3), 256>>>(Q, K, V, Wq, Wk, Wv);
    flash_kernel<<<dim3(NW / 64, NH, NB), 256, smem>>>();
    out_gemm_kernel<<<dim3(DM / 64, MT / 64), 256>>>(Wo, out);
}

// round 3
// speedup vs baseline: 1.3892x; 1.3892x over previous
#include <cuda_runtime.h>
#include <cuda_bf16.h>
#include <cstdint>
#include <math.h>

#define NB 4
#define NW 2048
#define DM 1024
#define NH 16
#define DK 64
#define MT (NB*NW)          // 8192 rows
#define MWPR (NW/32)
#define FROW 68

// ---------------- device scratch ----------------
__device__ float g_q[NB*NH*NW*DK];
__device__ float g_k[NB*NH*NW*DK];
__device__ float g_v[NB*NH*NW*DK];
__device__ float g_attn[NB*NW*DM];
__device__ unsigned g_mb[NB*NW*MWPR];
__device__ __nv_bfloat16 g_xh[3u*MT*DM];   // hi parts of Q,K,V inputs (slot 0 reused for attn)
__device__ __nv_bfloat16 g_xl[3u*MT*DM];
__device__ __nv_bfloat16 g_wh[4u*DM*DM];   // Wq,Wk,Wv,Wo hi
__device__ __nv_bfloat16 g_wl[4u*DM*DM];

// ---------------- PTX helpers (target-portable: no 'a' features) ----------------
__device__ __forceinline__ uint32_t smem_u32(const void* p) {
    uint32_t a;
    asm("{ .reg .u64 t; cvta.to.shared.u64 t, %1; cvt.u32.u64 %0, t; }" : "=r"(a) : "l"(p));
    return a;
}
#define CP_ASYNC16(sa, g) \
    asm volatile("cp.async.cg.shared.global [%0], [%1], 16;" :: "r"(sa), "l"(g))
#define CP_COMMIT() asm volatile("cp.async.commit_group;" ::: "memory")
#define CP_WAIT1()  asm volatile("cp.async.wait_group 1;" ::: "memory")
#define CP_WAIT0()  asm volatile("cp.async.wait_group 0;" ::: "memory")

#define LDSM4(r, addr) \
    asm volatile("ldmatrix.sync.aligned.m8n8.x4.shared.b16 {%0,%1,%2,%3}, [%4];" \
        : "=r"((r)[0]), "=r"((r)[1]), "=r"((r)[2]), "=r"((r)[3]) : "r"(addr))

#define MMA16816(d, a, b0, b1) \
    asm volatile("mma.sync.aligned.m16n8k16.row.col.f32.bf16.bf16.f32 " \
        "{%0,%1,%2,%3}, {%4,%5,%6,%7}, {%8,%9}, {%0,%1,%2,%3};" \
        : "+f"((d)[0]), "+f"((d)[1]), "+f"((d)[2]), "+f"((d)[3]) \
        : "r"((a)[0]), "r"((a)[1]), "r"((a)[2]), "r"((a)[3]), "r"(b0), "r"(b1))

// SMEM geometry: per stage 4 tiles (Xh,Xl,Wh,Wl) of 128 rows x 32 bf16, row stride 40
#define BKC   32
#define RS    40                        // padded row stride (80B: conflict-free for ldmatrix)
#define TS    (128*RS)                  // 5120 bf16 per tile
#define STAGE (4*TS)                    // bf16 per stage
#define SMEM_MMA (2*STAGE*2)            // bytes = 81920

// ============================================================
// pack mask -> bits
// ============================================================
__global__ void __launch_bounds__(256) pack_mask_kernel(const int* __restrict__ mask) {
    int gt = blockIdx.x * 256 + threadIdx.x;
    int word = gt >> 5, lane = gt & 31;
    int v = mask[word * 32 + lane];
    unsigned b = __ballot_sync(0xffffffffu, v != 0);
    if (lane == 0) g_mb[word] = b;
}

// ============================================================
// fp32 -> (hi, lo) bf16 split
// ============================================================
__global__ void __launch_bounds__(256) conv_kernel(const float* __restrict__ src,
                                                   __nv_bfloat16* __restrict__ hi,
                                                   __nv_bfloat16* __restrict__ lo) {
    int i = (blockIdx.x * 256 + threadIdx.x) * 4;
    float4 v = *(const float4*)(src + i);
    __nv_bfloat16 h0 = __float2bfloat16(v.x), h1 = __float2bfloat16(v.y);
    __nv_bfloat16 h2 = __float2bfloat16(v.z), h3 = __float2bfloat16(v.w);
    __nv_bfloat16 l0 = __float2bfloat16(v.x - __bfloat162float(h0));
    __nv_bfloat16 l1 = __float2bfloat16(v.y - __bfloat162float(h1));
    __nv_bfloat16 l2 = __float2bfloat16(v.z - __bfloat162float(h2));
    __nv_bfloat16 l3 = __float2bfloat16(v.w - __bfloat162float(h3));
    ((__nv_bfloat162*)(hi + i))[0] = __nv_bfloat162(h0, h1);
    ((__nv_bfloat162*)(hi + i))[1] = __nv_bfloat162(h2, h3);
    ((__nv_bfloat162*)(lo + i))[0] = __nv_bfloat162(l0, l1);
    ((__nv_bfloat162*)(lo + i))[1] = __nv_bfloat162(l2, l3);
}

// ============================================================
// cp.async stage issue: 8 x 16B chunks per thread
// tiles: 0=Xh 1=Xl 2=Wh 3=Wl
// ============================================================
__device__ __forceinline__ void issue_stage(
    const __nv_bfloat16* __restrict__ xh, const __nv_bfloat16* __restrict__ xl,
    const __nv_bfloat16* __restrict__ wh, const __nv_bfloat16* __restrict__ wl,
    int m0, int n0, int kt, uint32_t stage_sb, int tid)
{
    const __nv_bfloat16* gb[4] = { xh, xl, wh, wl };
    int rb[4] = { m0, m0, n0, n0 };
    #pragma unroll
    for (int t = 0; t < 8; t++) {
        int tile = t >> 1;
        int rem = tid + (t & 1) * 256;        // 0..511
        int row = rem >> 2, cq = rem & 3;
        const __nv_bfloat16* g = gb[tile] + (size_t)(rb[tile] + row) * DM + kt * BKC + cq * 8;
        uint32_t sa = stage_sb + (uint32_t)(tile * TS + row * RS + cq * 8) * 2;
        CP_ASYNC16(sa, g);
    }
}

// ============================================================
// Core: C[128x128] = X[m0:+128,:] * W[n0:+128,:]^T via 3-term split-bf16 mma.sync
// acc layout: acc[mi][nj][4]
// ============================================================
__device__ __forceinline__ void mma_mainloop(
    const __nv_bfloat16* __restrict__ xh, const __nv_bfloat16* __restrict__ xl,
    const __nv_bfloat16* __restrict__ wh, const __nv_bfloat16* __restrict__ wl,
    int m0, int n0, __nv_bfloat16* sbuf, float acc[4][4][4])
{
    int tid = threadIdx.x;
    int wid = tid >> 5, lane = tid & 31;
    int wm = wid >> 2, wn = wid & 3;          // 2 x 4 warp grid
    int lr = lane & 15, lc = lane >> 4;       // ldmatrix x4 addressing

    uint32_t sb = smem_u32(sbuf);
    uint32_t stage_sb[2] = { sb, sb + (uint32_t)STAGE * 2 };

    issue_stage(xh, xl, wh, wl, m0, n0, 0, stage_sb[0], tid);
    CP_COMMIT();

    for (int kt = 0; kt < DM / BKC; kt++) {
        int s = kt & 1;
        if (kt < DM / BKC - 1) {
            issue_stage(xh, xl, wh, wl, m0, n0, kt + 1, stage_sb[s ^ 1], tid);
            CP_COMMIT();
            CP_WAIT1();
        } else {
            CP_WAIT0();
        }
        __syncthreads();

        uint32_t ab = stage_sb[s];
        #pragma unroll
        for (int kk = 0; kk < BKC; kk += 16) {
            uint32_t ah[4][4], al[4][4];
            #pragma unroll
            for (int mi = 0; mi < 4; mi++) {
                uint32_t off = (uint32_t)((wm * 64 + mi * 16 + lr) * RS + kk + lc * 8) * 2;
                LDSM4(ah[mi], ab + off);                    // Xh tile
                LDSM4(al[mi], ab + (uint32_t)TS * 2 + off); // Xl tile
            }
            uint32_t bh[2][4], bl[2][4];
            #pragma unroll
            for (int ni = 0; ni < 2; ni++) {
                uint32_t off = (uint32_t)((wn * 32 + ni * 16 + lr) * RS + kk + lc * 8) * 2;
                LDSM4(bh[ni], ab + (uint32_t)(2 * TS) * 2 + off); // Wh
                LDSM4(bl[ni], ab + (uint32_t)(3 * TS) * 2 + off); // Wl
            }
            #pragma unroll
            for (int mi = 0; mi < 4; mi++)
                #pragma unroll
                for (int nj = 0; nj < 4; nj++) {
                    int ni = nj >> 1, hf = nj & 1;
                    MMA16816(acc[mi][nj], ah[mi], bh[ni][hf], bh[ni][hf + 2]);
                    MMA16816(acc[mi][nj], ah[mi], bl[ni][hf], bl[ni][hf + 2]);
                    MMA16816(acc[mi][nj], al[mi], bh[ni][hf], bh[ni][hf + 2]);
                }
        }
        __syncthreads();
    }
}

// ============================================================
// Projection GEMM: z = 0/1/2 selects Q/K/V; epilogue head-major fp32
// ============================================================
__global__ void __launch_bounds__(256) proj_mma_kernel() {
    extern __shared__ __nv_bfloat16 sbuf[];
    int z = blockIdx.z;
    int m0 = blockIdx.y * 128, n0 = blockIdx.x * 128;
    const __nv_bfloat16* xh = g_xh + (size_t)z * MT * DM;
    const __nv_bfloat16* xl = g_xl + (size_t)z * MT * DM;
    const __nv_bfloat16* wh = g_wh + (size_t)z * DM * DM;
    const __nv_bfloat16* wl = g_wl + (size_t)z * DM * DM;
    float* dst = (z == 0) ? g_q : (z == 1) ? g_k : g_v;

    float acc[4][4][4];
    #pragma unroll
    for (int i = 0; i < 4; i++)
        #pragma unroll
        for (int j = 0; j < 4; j++)
            acc[i][j][0] = acc[i][j][1] = acc[i][j][2] = acc[i][j][3] = 0.f;

    mma_mainloop(xh, xl, wh, wl, m0, n0, sbuf, acc);

    int tid = threadIdx.x, wid = tid >> 5, lane = tid & 31;
    int wm = wid >> 2, wn = wid & 3;
    #pragma unroll
    for (int mi = 0; mi < 4; mi++)
        #pragma unroll
        for (int nj = 0; nj < 4; nj++) {
            int n = n0 + wn * 32 + nj * 8 + (lane & 3) * 2;
            int h = n >> 6, d = n & 63;
            int m = m0 + wm * 64 + mi * 16 + (lane >> 2);
            int b = m >> 11, t = m & (NW - 1);
            float* p0 = dst + ((size_t)(b * NH + h) * NW + t) * DK + d;
            *(float2*)p0 = make_float2(acc[mi][nj][0], acc[mi][nj][1]);
            float* p1 = dst + ((size_t)(b * NH + h) * NW + (t + 8)) * DK + d;  // m+8 same b
            *(float2*)p1 = make_float2(acc[mi][nj][2], acc[mi][nj][3]);
        }
}

// ============================================================
// Output GEMM: attn(split bf16 slot 0) @ Wo^T -> out fp32 row-major
// ============================================================
__global__ void __launch_bounds__(256) out_mma_kernel(float* __restrict__ out) {
    extern __shared__ __nv_bfloat16 sbuf[];
    int m0 = blockIdx.y * 128, n0 = blockIdx.x * 128;
    const __nv_bfloat16* wh = g_wh + (size_t)3 * DM * DM;
    const __nv_bfloat16* wl = g_wl + (size_t)3 * DM * DM;

    float acc[4][4][4];
    #pragma unroll
    for (int i = 0; i < 4; i++)
        #pragma unroll
        for (int j = 0; j < 4; j++)
            acc[i][j][0] = acc[i][j][1] = acc[i][j][2] = acc[i][j][3] = 0.f;

    mma_mainloop(g_xh, g_xl, wh, wl, m0, n0, sbuf, acc);

    int tid = threadIdx.x, wid = tid >> 5, lane = tid & 31;
    int wm = wid >> 2, wn = wid & 3;
    #pragma unroll
    for (int mi = 0; mi < 4; mi++)
        #pragma unroll
        for (int nj = 0; nj < 4; nj++) {
            int n = n0 + wn * 32 + nj * 8 + (lane & 3) * 2;
            int m = m0 + wm * 64 + mi * 16 + (lane >> 2);
            *(float2*)(out + (size_t)m * DM + n) = make_float2(acc[mi][nj][0], acc[mi][nj][1]);
            *(float2*)(out + (size_t)(m + 8) * DM + n) = make_float2(acc[mi][nj][2], acc[mi][nj][3]);
        }
}

// ============================================================
// Flash attention (fp32 SIMT) — round-1 passing version, unchanged
// ============================================================
__global__ void __launch_bounds__(256) flash_kernel() {
    extern __shared__ float sm[];
    float* Qs  = sm;
    float* KPs = sm + 64 * FROW;
    float* Vs  = sm + 2 * 64 * FROW;
    unsigned* mw = (unsigned*)(sm + 3 * 64 * FROW);

    int b = blockIdx.z, h = blockIdx.y, q0 = blockIdx.x * 64;
    int tid = threadIdx.x;
    int ty = tid >> 4, tx = tid & 15;

    const float* qp = g_q + ((size_t)(b * NH + h) * NW + q0) * DK;
    const float* kb = g_k + (size_t)(b * NH + h) * NW * DK;
    const float* vb = g_v + (size_t)(b * NH + h) * NW * DK;

    #pragma unroll
    for (int it = 0; it < 4; it++) {
        int idx = tid + it * 256;
        int m = idx >> 4, dq = idx & 15;
        float4 v = *(const float4*)&qp[m * DK + dq * 4];
        Qs[(dq*4+0)*FROW + m] = v.x * 0.125f;
        Qs[(dq*4+1)*FROW + m] = v.y * 0.125f;
        Qs[(dq*4+2)*FROW + m] = v.z * 0.125f;
        Qs[(dq*4+3)*FROW + m] = v.w * 0.125f;
    }

    float om[4], ol[4], acc[4][4];
    #pragma unroll
    for (int i = 0; i < 4; i++) {
        om[i] = -INFINITY; ol[i] = 0.f;
        #pragma unroll
        for (int j = 0; j < 4; j++) acc[i][j] = 0.f;
    }

    for (int kt = 0; kt < NW / 64; kt++) {
        __syncthreads();
        const float* kp = kb + kt * 64 * DK;
        const float* vp = vb + kt * 64 * DK;
        #pragma unroll
        for (int it = 0; it < 4; it++) {
            int idx = tid + it * 256;
            int n = idx >> 4, dq = idx & 15;
            float4 kv = *(const float4*)&kp[n * DK + dq * 4];
            KPs[(dq*4+0)*FROW + n] = kv.x;
            KPs[(dq*4+1)*FROW + n] = kv.y;
            KPs[(dq*4+2)*FROW + n] = kv.z;
            KPs[(dq*4+3)*FROW + n] = kv.w;
            float4 vv = *(const float4*)&vp[n * DK + dq * 4];
            *(float4*)&Vs[n * FROW + dq * 4] = vv;
        }
        if (tid < 128) {
            int r = tid >> 1, w = tid & 1;
            mw[r * 2 + w] = g_mb[(size_t)(b * NW + q0 + r) * MWPR + kt * 2 + w];
        }
        __syncthreads();

        float s[4][4] = {};
        #pragma unroll 16
        for (int d = 0; d < DK; d++) {
            float4 a4 = *(const float4*)&Qs[d * FROW + ty * 4];
            float4 b4 = *(const float4*)&KPs[d * FROW + tx * 4];
            float a[4] = {a4.x, a4.y, a4.z, a4.w};
            float bb[4] = {b4.x, b4.y, b4.z, b4.w};
            #pragma unroll
            for (int i = 0; i < 4; i++)
                #pragma unroll
                for (int j = 0; j < 4; j++)
                    s[i][j] += a[i] * bb[j];
        }

        float tm[4], rs[4];
        #pragma unroll
        for (int i = 0; i < 4; i++) {
            unsigned w0 = mw[(ty*4+i)*2 + 0];
            unsigned w1 = mw[(ty*4+i)*2 + 1];
            tm[i] = -INFINITY;
            #pragma unroll
            for (int j = 0; j < 4; j++) {
                int n = tx * 4 + j;
                unsigned bits = (n < 32) ? w0 : w1;
                if (!((bits >> (n & 31)) & 1u)) s[i][j] = -1e9f;
                tm[i] = fmaxf(tm[i], s[i][j]);
            }
        }
        #pragma unroll
        for (int i = 0; i < 4; i++) {
            tm[i] = fmaxf(tm[i], __shfl_xor_sync(0xffffffffu, tm[i], 8));
            tm[i] = fmaxf(tm[i], __shfl_xor_sync(0xffffffffu, tm[i], 4));
            tm[i] = fmaxf(tm[i], __shfl_xor_sync(0xffffffffu, tm[i], 2));
            tm[i] = fmaxf(tm[i], __shfl_xor_sync(0xffffffffu, tm[i], 1));
        }
        #pragma unroll
        for (int i = 0; i < 4; i++) {
            float nm = fmaxf(om[i], tm[i]);
            float sc = __expf(om[i] - nm);
            rs[i] = 0.f;
            #pragma unroll
            for (int j = 0; j < 4; j++) {
                s[i][j] = __expf(s[i][j] - nm);
                rs[i] += s[i][j];
            }
            om[i] = nm;
            ol[i] *= sc;
            #pragma unroll
            for (int j = 0; j < 4; j++) acc[i][j] *= sc;
        }
        #pragma unroll
        for (int i = 0; i < 4; i++) {
            rs[i] += __shfl_xor_sync(0xffffffffu, rs[i], 8);
            rs[i] += __shfl_xor_sync(0xffffffffu, rs[i], 4);
            rs[i] += __shfl_xor_sync(0xffffffffu, rs[i], 2);
            rs[i] += __shfl_xor_sync(0xffffffffu, rs[i], 1);
            ol[i] += rs[i];
        }

        __syncthreads();
        #pragma unroll
        for (int i = 0; i < 4; i++)
            #pragma unroll
            for (int j = 0; j < 4; j++)
                KPs[(tx*4+j)*FROW + ty*4+i] = s[i][j];
        __syncthreads();

        #pragma unroll 16
        for (int n = 0; n < 64; n++) {
            float4 a4 = *(const float4*)&KPs[n * FROW + ty * 4];
            float4 v4 = *(const float4*)&Vs[n * FROW + tx * 4];
            float a[4] = {a4.x, a4.y, a4.z, a4.w};
            float vv[4] = {v4.x, v4.y, v4.z, v4.w};
            #pragma unroll
            for (int i = 0; i < 4; i++)
                #pragma unroll
                for (int j = 0; j < 4; j++)
                    acc[i][j] += a[i] * vv[j];
        }
    }

    #pragma unroll
    for (int i = 0; i < 4; i++) {
        float inv = 1.f / ol[i];
        int t = q0 + ty * 4 + i;
        float4 o = make_float4(acc[i][0]*inv, acc[i][1]*inv, acc[i][2]*inv, acc[i][3]*inv);
        *(float4*)&g_attn[(size_t)(b * NW + t) * DM + h * DK + tx * 4] = o;
    }
}

// ============================================================
extern "C" void kernel_launch(void* const* d_in, const int* in_sizes, int n_in,
                              void* d_out, int out_size) {
    const float* Q  = (const float*)d_in[0];
    const float* K  = (const float*)d_in[1];
    const float* V  = (const float*)d_in[2];
    const int* mask = (const int*)d_in[3];
    const float* Wq = (const float*)d_in[4];
    const float* Wk = (const float*)d_in[5];
    const float* Wv = (const float*)d_in[6];
    const float* Wo = (const float*)d_in[7];
    float* out = (float*)d_out;

    size_t fsm = (size_t)(3 * 64 * FROW + 128) * sizeof(float);
    static int attr_done = 0;
    if (!attr_done) {
        cudaFuncSetAttribute(flash_kernel, cudaFuncAttributeMaxDynamicSharedMemorySize, (int)fsm);
        cudaFuncSetAttribute(proj_mma_kernel, cudaFuncAttributeMaxDynamicSharedMemorySize, SMEM_MMA);
        cudaFuncSetAttribute(out_mma_kernel, cudaFuncAttributeMaxDynamicSharedMemorySize, SMEM_MMA);
        attr_done = 1;
    }

    __nv_bfloat16 *xh, *xl, *wh, *wl;
    float* attn;
    cudaGetSymbolAddress((void**)&xh, g_xh);
    cudaGetSymbolAddress((void**)&xl, g_xl);
    cudaGetSymbolAddress((void**)&wh, g_wh);
    cudaGetSymbolAddress((void**)&wl, g_wl);
    cudaGetSymbolAddress((void**)&attn, g_attn);

    const size_t NX = (size_t)MT * DM;   // 8M
    const size_t NWT = (size_t)DM * DM;  // 1M

    pack_mask_kernel<<<(NB * NW * NW) / 256, 256>>>(mask);

    conv_kernel<<<NX / 1024, 256>>>(Q, xh, xl);
    conv_kernel<<<NX / 1024, 256>>>(K, xh + NX, xl + NX);
    conv_kernel<<<NX / 1024, 256>>>(V, xh + 2 * NX, xl + 2 * NX);
    conv_kernel<<<NWT / 1024, 256>>>(Wq, wh, wl);
    conv_kernel<<<NWT / 1024, 256>>>(Wk, wh + NWT, wl + NWT);
    conv_kernel<<<NWT / 1024, 256>>>(Wv, wh + 2 * NWT, wl + 2 * NWT);
    conv_kernel<<<NWT / 1024, 256>>>(Wo, wh + 3 * NWT, wl + 3 * NWT);

    proj_mma_kernel<<<dim3(DM / 128, MT / 128, 3), 256, SMEM_MMA>>>();
    flash_kernel<<<dim3(NW / 64, NH, NB), 256, fsm>>>();
    conv_kernel<<<NX / 1024, 256>>>(attn, xh, xl);   // attn -> split bf16 slot 0
    out_mma_kernel<<<dim3(DM / 128, MT / 128), 256, SMEM_MMA>>>(out);
}

// round 4
// speedup vs baseline: 2.6569x; 1.9126x over previous
#include <cuda_runtime.h>
#include <cuda_bf16.h>
#include <cstdint>
#include <math.h>

#define NB 4
#define NW 2048
#define DM 1024
#define NH 16
#define DK 64
#define MT (NB*NW)          // 8192 rows
#define MWPR (NW/32)

// ---------------- device scratch ----------------
__device__ unsigned g_mb[NB*NW*MWPR];
__device__ __nv_bfloat16 g_xh[3u*MT*DM];   // hi of Q,K,V inputs (slot 0 reused for attn out)
__device__ __nv_bfloat16 g_xl[3u*MT*DM];
__device__ __nv_bfloat16 g_wh[4u*DM*DM];   // Wq,Wk,Wv,Wo hi
__device__ __nv_bfloat16 g_wl[4u*DM*DM];
// projected q/k/v, split bf16, head-major [b][h][t][d]
__device__ __nv_bfloat16 g_qh[NB*NH*NW*DK];
__device__ __nv_bfloat16 g_ql[NB*NH*NW*DK];
__device__ __nv_bfloat16 g_kh[NB*NH*NW*DK];
__device__ __nv_bfloat16 g_kl[NB*NH*NW*DK];
__device__ __nv_bfloat16 g_vh[NB*NH*NW*DK];
__device__ __nv_bfloat16 g_vl[NB*NH*NW*DK];

// ---------------- PTX helpers (target-portable) ----------------
__device__ __forceinline__ uint32_t smem_u32(const void* p) {
    uint32_t a;
    asm("{ .reg .u64 t; cvta.to.shared.u64 t, %1; cvt.u32.u64 %0, t; }" : "=r"(a) : "l"(p));
    return a;
}
#define CP_ASYNC16(sa, g) \
    asm volatile("cp.async.cg.shared.global [%0], [%1], 16;" :: "r"(sa), "l"(g))
#define CP_COMMIT() asm volatile("cp.async.commit_group;" ::: "memory")
#define CP_WAIT1()  asm volatile("cp.async.wait_group 1;" ::: "memory")
#define CP_WAIT0()  asm volatile("cp.async.wait_group 0;" ::: "memory")

#define LDSM4(r, addr) \
    asm volatile("ldmatrix.sync.aligned.m8n8.x4.shared.b16 {%0,%1,%2,%3}, [%4];" \
        : "=r"((r)[0]), "=r"((r)[1]), "=r"((r)[2]), "=r"((r)[3]) : "r"(addr))
#define LDSM4T(r, addr) \
    asm volatile("ldmatrix.sync.aligned.m8n8.x4.trans.shared.b16 {%0,%1,%2,%3}, [%4];" \
        : "=r"((r)[0]), "=r"((r)[1]), "=r"((r)[2]), "=r"((r)[3]) : "r"(addr))

#define MMA16816(d, a, b0, b1) \
    asm volatile("mma.sync.aligned.m16n8k16.row.col.f32.bf16.bf16.f32 " \
        "{%0,%1,%2,%3}, {%4,%5,%6,%7}, {%8,%9}, {%0,%1,%2,%3};" \
        : "+f"((d)[0]), "+f"((d)[1]), "+f"((d)[2]), "+f"((d)[3]) \
        : "r"((a)[0]), "r"((a)[1]), "r"((a)[2]), "r"((a)[3]), "r"(b0), "r"(b1))

// pack {low16=bf16(lo), high16=bf16(hi)}
#define PACK_BF16X2(r, lo, hi) \
    asm("cvt.rn.bf16x2.f32 %0, %1, %2;" : "=r"(r) : "f"(hi), "f"(lo))

// ---- GEMM smem geometry (round-3 proven) ----
#define BKC   32
#define RS    40
#define TS    (128*RS)
#define STAGE (4*TS)
#define SMEM_MMA (2*STAGE*2)

// ---- flash smem geometry ----
#define FRS    72                       // K/V smem row stride (bf16)
#define FTS    (64*FRS)                 // one 64x64 tile (padded)
#define FSTAGE (4*FTS)                  // Kh,Kl,Vh,Vl
#define SMEM_FLASH (2*FSTAGE*2)         // 73728 bytes

// ============================================================
__global__ void __launch_bounds__(256) pack_mask_kernel(const int* __restrict__ mask) {
    int gt = blockIdx.x * 256 + threadIdx.x;
    int word = gt >> 5, lane = gt & 31;
    int v = mask[word * 32 + lane];
    unsigned b = __ballot_sync(0xffffffffu, v != 0);
    if (lane == 0) g_mb[word] = b;
}

// ============================================================
__global__ void __launch_bounds__(256) conv_kernel(const float* __restrict__ src,
                                                   __nv_bfloat16* __restrict__ hi,
                                                   __nv_bfloat16* __restrict__ lo) {
    int i = (blockIdx.x * 256 + threadIdx.x) * 4;
    float4 v = *(const float4*)(src + i);
    __nv_bfloat16 h0 = __float2bfloat16(v.x), h1 = __float2bfloat16(v.y);
    __nv_bfloat16 h2 = __float2bfloat16(v.z), h3 = __float2bfloat16(v.w);
    __nv_bfloat16 l0 = __float2bfloat16(v.x - __bfloat162float(h0));
    __nv_bfloat16 l1 = __float2bfloat16(v.y - __bfloat162float(h1));
    __nv_bfloat16 l2 = __float2bfloat16(v.z - __bfloat162float(h2));
    __nv_bfloat16 l3 = __float2bfloat16(v.w - __bfloat162float(h3));
    ((__nv_bfloat162*)(hi + i))[0] = __nv_bfloat162(h0, h1);
    ((__nv_bfloat162*)(hi + i))[1] = __nv_bfloat162(h2, h3);
    ((__nv_bfloat162*)(lo + i))[0] = __nv_bfloat162(l0, l1);
    ((__nv_bfloat162*)(lo + i))[1] = __nv_bfloat162(l2, l3);
}

// ============================================================
// GEMM machinery (round-3, unchanged mainloop)
// ============================================================
__device__ __forceinline__ void issue_stage(
    const __nv_bfloat16* __restrict__ xh, const __nv_bfloat16* __restrict__ xl,
    const __nv_bfloat16* __restrict__ wh, const __nv_bfloat16* __restrict__ wl,
    int m0, int n0, int kt, uint32_t stage_sb, int tid)
{
    const __nv_bfloat16* gb[4] = { xh, xl, wh, wl };
    int rb[4] = { m0, m0, n0, n0 };
    #pragma unroll
    for (int t = 0; t < 8; t++) {
        int tile = t >> 1;
        int rem = tid + (t & 1) * 256;
        int row = rem >> 2, cq = rem & 3;
        const __nv_bfloat16* g = gb[tile] + (size_t)(rb[tile] + row) * DM + kt * BKC + cq * 8;
        uint32_t sa = stage_sb + (uint32_t)(tile * TS + row * RS + cq * 8) * 2;
        CP_ASYNC16(sa, g);
    }
}

__device__ __forceinline__ void mma_mainloop(
    const __nv_bfloat16* __restrict__ xh, const __nv_bfloat16* __restrict__ xl,
    const __nv_bfloat16* __restrict__ wh, const __nv_bfloat16* __restrict__ wl,
    int m0, int n0, __nv_bfloat16* sbuf, float acc[4][4][4])
{
    int tid = threadIdx.x;
    int wid = tid >> 5, lane = tid & 31;
    int wm = wid >> 2, wn = wid & 3;
    int lr = lane & 15, lc = lane >> 4;

    uint32_t sb = smem_u32(sbuf);
    uint32_t stage_sb[2] = { sb, sb + (uint32_t)STAGE * 2 };

    issue_stage(xh, xl, wh, wl, m0, n0, 0, stage_sb[0], tid);
    CP_COMMIT();

    for (int kt = 0; kt < DM / BKC; kt++) {
        int s = kt & 1;
        if (kt < DM / BKC - 1) {
            issue_stage(xh, xl, wh, wl, m0, n0, kt + 1, stage_sb[s ^ 1], tid);
            CP_COMMIT();
            CP_WAIT1();
        } else {
            CP_WAIT0();
        }
        __syncthreads();

        uint32_t ab = stage_sb[s];
        #pragma unroll
        for (int kk = 0; kk < BKC; kk += 16) {
            uint32_t ah[4][4], al[4][4];
            #pragma unroll
            for (int mi = 0; mi < 4; mi++) {
                uint32_t off = (uint32_t)((wm * 64 + mi * 16 + lr) * RS + kk + lc * 8) * 2;
                LDSM4(ah[mi], ab + off);
                LDSM4(al[mi], ab + (uint32_t)TS * 2 + off);
            }
            uint32_t bh[2][4], bl[2][4];
            #pragma unroll
            for (int ni = 0; ni < 2; ni++) {
                uint32_t off = (uint32_t)((wn * 32 + ni * 16 + lr) * RS + kk + lc * 8) * 2;
                LDSM4(bh[ni], ab + (uint32_t)(2 * TS) * 2 + off);
                LDSM4(bl[ni], ab + (uint32_t)(3 * TS) * 2 + off);
            }
            #pragma unroll
            for (int mi = 0; mi < 4; mi++)
                #pragma unroll
                for (int nj = 0; nj < 4; nj++) {
                    int ni = nj >> 1, hf = nj & 1;
                    MMA16816(acc[mi][nj], ah[mi], bh[ni][hf], bh[ni][hf + 2]);
                    MMA16816(acc[mi][nj], ah[mi], bl[ni][hf], bl[ni][hf + 2]);
                    MMA16816(acc[mi][nj], al[mi], bh[ni][hf], bh[ni][hf + 2]);
                }
        }
        __syncthreads();
    }
}

// ============================================================
// Projection GEMM: epilogue writes split-bf16 head-major q/k/v
// ============================================================
__global__ void __launch_bounds__(256) proj_mma_kernel() {
    extern __shared__ __nv_bfloat16 sbuf[];
    int z = blockIdx.z;
    int m0 = blockIdx.y * 128, n0 = blockIdx.x * 128;
    const __nv_bfloat16* xh = g_xh + (size_t)z * MT * DM;
    const __nv_bfloat16* xl = g_xl + (size_t)z * MT * DM;
    const __nv_bfloat16* wh = g_wh + (size_t)z * DM * DM;
    const __nv_bfloat16* wl = g_wl + (size_t)z * DM * DM;
    __nv_bfloat16* dh = (z == 0) ? g_qh : (z == 1) ? g_kh : g_vh;
    __nv_bfloat16* dl = (z == 0) ? g_ql : (z == 1) ? g_kl : g_vl;
    float scale = (z == 0) ? 0.125f : 1.0f;

    float acc[4][4][4];
    #pragma unroll
    for (int i = 0; i < 4; i++)
        #pragma unroll
        for (int j = 0; j < 4; j++)
            acc[i][j][0] = acc[i][j][1] = acc[i][j][2] = acc[i][j][3] = 0.f;

    mma_mainloop(xh, xl, wh, wl, m0, n0, sbuf, acc);

    int tid = threadIdx.x, wid = tid >> 5, lane = tid & 31;
    int wm = wid >> 2, wn = wid & 3;
    #pragma unroll
    for (int mi = 0; mi < 4; mi++)
        #pragma unroll
        for (int nj = 0; nj < 4; nj++) {
            int n = n0 + wn * 32 + nj * 8 + (lane & 3) * 2;
            int h = n >> 6, d = n & 63;
            int m = m0 + wm * 64 + mi * 16 + (lane >> 2);
            int bb = m >> 11, t = m & (NW - 1);
            size_t off = ((size_t)(bb * NH + h) * NW + t) * DK + d;
            float v0 = acc[mi][nj][0] * scale, v1 = acc[mi][nj][1] * scale;
            uint32_t hp, lp;
            PACK_BF16X2(hp, v0, v1);
            float f0 = __uint_as_float(hp << 16), f1 = __uint_as_float(hp & 0xffff0000u);
            PACK_BF16X2(lp, v0 - f0, v1 - f1);
            *(uint32_t*)(dh + off) = hp;
            *(uint32_t*)(dl + off) = lp;
            v0 = acc[mi][nj][2] * scale; v1 = acc[mi][nj][3] * scale;
            PACK_BF16X2(hp, v0, v1);
            f0 = __uint_as_float(hp << 16); f1 = __uint_as_float(hp & 0xffff0000u);
            PACK_BF16X2(lp, v0 - f0, v1 - f1);
            *(uint32_t*)(dh + off + 8 * DK) = hp;
            *(uint32_t*)(dl + off + 8 * DK) = lp;
        }
}

// ============================================================
// Output GEMM: attn(split bf16, slot 0) @ Wo^T -> out fp32
// ============================================================
__global__ void __launch_bounds__(256) out_mma_kernel(float* __restrict__ out) {
    extern __shared__ __nv_bfloat16 sbuf[];
    int m0 = blockIdx.y * 128, n0 = blockIdx.x * 128;
    const __nv_bfloat16* wh = g_wh + (size_t)3 * DM * DM;
    const __nv_bfloat16* wl = g_wl + (size_t)3 * DM * DM;

    float acc[4][4][4];
    #pragma unroll
    for (int i = 0; i < 4; i++)
        #pragma unroll
        for (int j = 0; j < 4; j++)
            acc[i][j][0] = acc[i][j][1] = acc[i][j][2] = acc[i][j][3] = 0.f;

    mma_mainloop(g_xh, g_xl, wh, wl, m0, n0, sbuf, acc);

    int tid = threadIdx.x, wid = tid >> 5, lane = tid & 31;
    int wm = wid >> 2, wn = wid & 3;
    #pragma unroll
    for (int mi = 0; mi < 4; mi++)
        #pragma unroll
        for (int nj = 0; nj < 4; nj++) {
            int n = n0 + wn * 32 + nj * 8 + (lane & 3) * 2;
            int m = m0 + wm * 64 + mi * 16 + (lane >> 2);
            *(float2*)(out + (size_t)m * DM + n) = make_float2(acc[mi][nj][0], acc[mi][nj][1]);
            *(float2*)(out + (size_t)(m + 8) * DM + n) = make_float2(acc[mi][nj][2], acc[mi][nj][3]);
        }
}

// ============================================================
// Flash attention on mma.sync (split bf16, 3-term)
// CTA: 128 q rows x one (b,h); 8 warps; warp owns 16 q rows.
// ============================================================
__device__ __forceinline__ void flash_issue(
    const __nv_bfloat16* __restrict__ kh, const __nv_bfloat16* __restrict__ kl,
    const __nv_bfloat16* __restrict__ vh, const __nv_bfloat16* __restrict__ vl,
    int kt, uint32_t stage_sb, int tid)
{
    const __nv_bfloat16* gb[4] = { kh, kl, vh, vl };
    #pragma unroll
    for (int t = 0; t < 8; t++) {
        int tile = t >> 1;
        int rem = tid + (t & 1) * 256;       // 0..511 within tile
        int row = rem >> 3, cq = rem & 7;
        const __nv_bfloat16* g = gb[tile] + (size_t)(kt * 64 + row) * DK + cq * 8;
        uint32_t sa = stage_sb + (uint32_t)(tile * FTS + row * FRS + cq * 8) * 2;
        CP_ASYNC16(sa, g);
    }
}

__global__ void __launch_bounds__(256) flash_mma_kernel() {
    extern __shared__ __nv_bfloat16 fsm[];
    int b = blockIdx.z, h = blockIdx.y, q0 = blockIdx.x * 128;
    int tid = threadIdx.x, wid = tid >> 5, lane = tid & 31;
    int lr = lane & 15, lc = lane >> 4;
    int gr = lane >> 2, c = lane & 3;

    size_t hb = (size_t)(b * NH + h) * NW * DK;
    const __nv_bfloat16* kh = g_kh + hb;
    const __nv_bfloat16* kl = g_kl + hb;
    const __nv_bfloat16* vh = g_vh + hb;
    const __nv_bfloat16* vl = g_vl + hb;
    const __nv_bfloat16* qh = g_qh + hb + (size_t)q0 * DK;
    const __nv_bfloat16* ql = g_ql + hb + (size_t)q0 * DK;

    // Q fragments straight from gmem (scale already folded in)
    uint32_t qhf[4][4], qlf[4][4];
    #pragma unroll
    for (int kc = 0; kc < 4; kc++) {
        int r0 = wid * 16 + gr, col = kc * 16 + 2 * c;
        qhf[kc][0] = *(const uint32_t*)(qh + (size_t)r0 * DK + col);
        qhf[kc][1] = *(const uint32_t*)(qh + (size_t)(r0 + 8) * DK + col);
        qhf[kc][2] = *(const uint32_t*)(qh + (size_t)r0 * DK + col + 8);
        qhf[kc][3] = *(const uint32_t*)(qh + (size_t)(r0 + 8) * DK + col + 8);
        qlf[kc][0] = *(const uint32_t*)(ql + (size_t)r0 * DK + col);
        qlf[kc][1] = *(const uint32_t*)(ql + (size_t)(r0 + 8) * DK + col);
        qlf[kc][2] = *(const uint32_t*)(ql + (size_t)r0 * DK + col + 8);
        qlf[kc][3] = *(const uint32_t*)(ql + (size_t)(r0 + 8) * DK + col + 8);
    }

    float oacc[8][4];
    #pragma unroll
    for (int j = 0; j < 8; j++)
        oacc[j][0] = oacc[j][1] = oacc[j][2] = oacc[j][3] = 0.f;
    float m0 = -INFINITY, m1 = -INFINITY, l0 = 0.f, l1 = 0.f;

    uint32_t sb = smem_u32(fsm);
    flash_issue(kh, kl, vh, vl, 0, sb, tid);
    CP_COMMIT();

    for (int kt = 0; kt < NW / 64; kt++) {
        int s = kt & 1;
        uint32_t ss = sb + (uint32_t)(s * FSTAGE) * 2;
        if (kt < NW / 64 - 1) {
            flash_issue(kh, kl, vh, vl, kt + 1, sb + (uint32_t)((s ^ 1) * FSTAGE) * 2, tid);
            CP_COMMIT();
            CP_WAIT1();
        } else {
            CP_WAIT0();
        }
        __syncthreads();

        // mask words for this thread's two rows
        const unsigned* mb0 = g_mb + (size_t)(b * NW + q0 + wid * 16 + gr) * MWPR + kt * 2;
        unsigned mw00 = mb0[0], mw01 = mb0[1];
        unsigned mw10 = mb0[8 * MWPR], mw11 = mb0[8 * MWPR + 1];

        // ---- S = Q K^T (3-term) ----
        float sacc[8][4];
        #pragma unroll
        for (int j = 0; j < 8; j++)
            sacc[j][0] = sacc[j][1] = sacc[j][2] = sacc[j][3] = 0.f;

        #pragma unroll
        for (int kc = 0; kc < 4; kc++) {
            #pragma unroll
            for (int g = 0; g < 4; g++) {
                uint32_t khf[4], klf[4];
                uint32_t off = (uint32_t)((g * 16 + lr) * FRS + kc * 16 + lc * 8) * 2;
                LDSM4(khf, ss + off);
                LDSM4(klf, ss + (uint32_t)FTS * 2 + off);
                #pragma unroll
                for (int hf = 0; hf < 2; hf++) {
                    MMA16816(sacc[2 * g + hf], qhf[kc], khf[hf], khf[hf + 2]);
                    MMA16816(sacc[2 * g + hf], qhf[kc], klf[hf], klf[hf + 2]);
                    MMA16816(sacc[2 * g + hf], qlf[kc], khf[hf], khf[hf + 2]);
                }
            }
        }

        // ---- mask ----
        #pragma unroll
        for (int j = 0; j < 8; j++) {
            unsigned wr0 = (j < 4) ? mw00 : mw01;
            unsigned wr1 = (j < 4) ? mw10 : mw11;
            int bit = (8 * j + 2 * c) & 31;
            if (!((wr0 >> bit) & 1u))       sacc[j][0] = -1e9f;
            if (!((wr0 >> (bit + 1)) & 1u)) sacc[j][1] = -1e9f;
            if (!((wr1 >> bit) & 1u))       sacc[j][2] = -1e9f;
            if (!((wr1 >> (bit + 1)) & 1u)) sacc[j][3] = -1e9f;
        }

        // ---- online softmax ----
        float mx0 = -INFINITY, mx1 = -INFINITY;
        #pragma unroll
        for (int j = 0; j < 8; j++) {
            mx0 = fmaxf(mx0, fmaxf(sacc[j][0], sacc[j][1]));
            mx1 = fmaxf(mx1, fmaxf(sacc[j][2], sacc[j][3]));
        }
        mx0 = fmaxf(mx0, __shfl_xor_sync(0xffffffffu, mx0, 1));
        mx0 = fmaxf(mx0, __shfl_xor_sync(0xffffffffu, mx0, 2));
        mx1 = fmaxf(mx1, __shfl_xor_sync(0xffffffffu, mx1, 1));
        mx1 = fmaxf(mx1, __shfl_xor_sync(0xffffffffu, mx1, 2));

        float nm0 = fmaxf(m0, mx0), nm1 = fmaxf(m1, mx1);
        float sc0 = __expf(m0 - nm0), sc1 = __expf(m1 - nm1);
        float rs0 = 0.f, rs1 = 0.f;
        #pragma unroll
        for (int j = 0; j < 8; j++) {
            sacc[j][0] = __expf(sacc[j][0] - nm0);
            sacc[j][1] = __expf(sacc[j][1] - nm0);
            sacc[j][2] = __expf(sacc[j][2] - nm1);
            sacc[j][3] = __expf(sacc[j][3] - nm1);
            rs0 += sacc[j][0] + sacc[j][1];
            rs1 += sacc[j][2] + sacc[j][3];
        }
        rs0 += __shfl_xor_sync(0xffffffffu, rs0, 1);
        rs0 += __shfl_xor_sync(0xffffffffu, rs0, 2);
        rs1 += __shfl_xor_sync(0xffffffffu, rs1, 1);
        rs1 += __shfl_xor_sync(0xffffffffu, rs1, 2);
        m0 = nm0; m1 = nm1;
        l0 = l0 * sc0 + rs0;
        l1 = l1 * sc1 + rs1;
        #pragma unroll
        for (int j = 0; j < 8; j++) {
            oacc[j][0] *= sc0; oacc[j][1] *= sc0;
            oacc[j][2] *= sc1; oacc[j][3] *= sc1;
        }

        // ---- pack P into split-bf16 A fragments ----
        uint32_t phf[4][4], plf[4][4];
        #pragma unroll
        for (int kc = 0; kc < 4; kc++) {
            #pragma unroll
            for (int q = 0; q < 4; q++) {
                int jt = 2 * kc + (q >> 1);
                int e0 = (q & 1) * 2, e1 = e0 + 1;   // q0:{[0],[1]} q1:{[2],[3]}
                float p0 = sacc[jt][(q & 1) ? 2 : 0];
                float p1 = sacc[jt][(q & 1) ? 3 : 1];
                uint32_t hp, lp;
                PACK_BF16X2(hp, p0, p1);
                float f0 = __uint_as_float(hp << 16);
                float f1 = __uint_as_float(hp & 0xffff0000u);
                PACK_BF16X2(lp, p0 - f0, p1 - f1);
                phf[kc][q] = hp; plf[kc][q] = lp;
                (void)e0; (void)e1;
            }
        }

        // ---- O += P V (3-term), V via ldmatrix.trans ----
        #pragma unroll
        for (int kc = 0; kc < 4; kc++) {
            #pragma unroll
            for (int dg = 0; dg < 4; dg++) {
                uint32_t vhf[4], vlf[4];
                uint32_t off = (uint32_t)((kc * 16 + lr) * FRS + dg * 16 + lc * 8) * 2;
                LDSM4T(vhf, ss + (uint32_t)(2 * FTS) * 2 + off);
                LDSM4T(vlf, ss + (uint32_t)(3 * FTS) * 2 + off);
                MMA16816(oacc[2 * dg],     phf[kc], vhf[0], vhf[1]);
                MMA16816(oacc[2 * dg],     plf[kc], vhf[0], vhf[1]);
                MMA16816(oacc[2 * dg],     phf[kc], vlf[0], vlf[1]);
                MMA16816(oacc[2 * dg + 1], phf[kc], vhf[2], vhf[3]);
                MMA16816(oacc[2 * dg + 1], plf[kc], vhf[2], vhf[3]);
                MMA16816(oacc[2 * dg + 1], phf[kc], vlf[2], vlf[3]);
            }
        }
        __syncthreads();
    }

    // ---- epilogue: normalize, split hi/lo, write to out-GEMM input slot 0 ----
    float inv0 = 1.f / l0, inv1 = 1.f / l1;
    int row0 = q0 + wid * 16 + gr;
    size_t base0 = ((size_t)b * NW + row0) * DM + h * DK;
    #pragma unroll
    for (int j = 0; j < 8; j++) {
        int d = 8 * j + 2 * c;
        float v0 = oacc[j][0] * inv0, v1 = oacc[j][1] * inv0;
        uint32_t hp, lp;
        PACK_BF16X2(hp, v0, v1);
        float f0 = __uint_as_float(hp << 16), f1 = __uint_as_float(hp & 0xffff0000u);
        PACK_BF16X2(lp, v0 - f0, v1 - f1);
        *(uint32_t*)((__nv_bfloat16*)g_xh + base0 + d) = hp;
        *(uint32_t*)((__nv_bfloat16*)g_xl + base0 + d) = lp;
        v0 = oacc[j][2] * inv1; v1 = oacc[j][3] * inv1;
        PACK_BF16X2(hp, v0, v1);
        f0 = __uint_as_float(hp << 16); f1 = __uint_as_float(hp & 0xffff0000u);
        PACK_BF16X2(lp, v0 - f0, v1 - f1);
        *(uint32_t*)((__nv_bfloat16*)g_xh + base0 + 8 * DM + d) = hp;
        *(uint32_t*)((__nv_bfloat16*)g_xl + base0 + 8 * DM + d) = lp;
    }
}

// ============================================================
extern "C" void kernel_launch(void* const* d_in, const int* in_sizes, int n_in,
                              void* d_out, int out_size) {
    const float* Q  = (const float*)d_in[0];
    const float* K  = (const float*)d_in[1];
    const float* V  = (const float*)d_in[2];
    const int* mask = (const int*)d_in[3];
    const float* Wq = (const float*)d_in[4];
    const float* Wk = (const float*)d_in[5];
    const float* Wv = (const float*)d_in[6];
    const float* Wo = (const float*)d_in[7];
    float* out = (float*)d_out;

    static int attr_done = 0;
    if (!attr_done) {
        cudaFuncSetAttribute(proj_mma_kernel, cudaFuncAttributeMaxDynamicSharedMemorySize, SMEM_MMA);
        cudaFuncSetAttribute(out_mma_kernel, cudaFuncAttributeMaxDynamicSharedMemorySize, SMEM_MMA);
        cudaFuncSetAttribute(flash_mma_kernel, cudaFuncAttributeMaxDynamicSharedMemorySize, SMEM_FLASH);
        attr_done = 1;
    }

    __nv_bfloat16 *xh, *xl, *wh, *wl;
    cudaGetSymbolAddress((void**)&xh, g_xh);
    cudaGetSymbolAddress((void**)&xl, g_xl);
    cudaGetSymbolAddress((void**)&wh, g_wh);
    cudaGetSymbolAddress((void**)&wl, g_wl);

    const size_t NX = (size_t)MT * DM;   // 8M
    const size_t NWT = (size_t)DM * DM;  // 1M

    pack_mask_kernel<<<(NB * NW * NW) / 256, 256>>>(mask);

    conv_kernel<<<NX / 1024, 256>>>(Q, xh, xl);
    conv_kernel<<<NX / 1024, 256>>>(K, xh + NX, xl + NX);
    conv_kernel<<<NX / 1024, 256>>>(V, xh + 2 * NX, xl + 2 * NX);
    conv_kernel<<<NWT / 1024, 256>>>(Wq, wh, wl);
    conv_kernel<<<NWT / 1024, 256>>>(Wk, wh + NWT, wl + NWT);
    conv_kernel<<<NWT / 1024, 256>>>(Wv, wh + 2 * NWT, wl + 2 * NWT);
    conv_kernel<<<NWT / 1024, 256>>>(Wo, wh + 3 * NWT, wl + 3 * NWT);

    proj_mma_kernel<<<dim3(DM / 128, MT / 128, 3), 256, SMEM_MMA>>>();
    flash_mma_kernel<<<dim3(NW / 128, NH, NB), 256, SMEM_FLASH>>>();
    out_mma_kernel<<<dim3(DM / 128, MT / 128), 256, SMEM_MMA>>>(out);
}